// round 5
// baseline (speedup 1.0000x reference)
#include <cuda_runtime.h>
#include <cuda.h>
#include <cstdint>

// ============================================================================
// Problem constants
// ============================================================================
#define NN      8192
#define DD      128

// GEMM config (Ampere-style mma.sync tf32; baseline PTX, compiles for sm_100)
#define BM      64
#define BN      128
#define BK      32
#define STAGES  5
#define NKT     (NN / BK)      // 256 K iterations
#define GTHREADS 512           // 16 warps: 4 along M x 4 along N, warp tile 16x32

// SMEM tile strides (floats); +4 pad keeps LDS conflict-free and 16B-aligned rows
#define APAD    36             // 32 + 4
#define AS_FLOATS (BM * APAD)          // 2304
#define BS_FLOATS (BN * APAD)          // 4608
#define STAGE_FLOATS (AS_FLOATS + BS_FLOATS)   // 6912
#define SMEM_TOTAL (STAGES * STAGE_FLOATS * 4) // 138240 bytes

// ============================================================================
// Scratch (device globals; allocation-free)
// ============================================================================
__device__ __align__(1024) float g_h[NN * DD];
__device__ __align__(1024) float g_g[NN * DD];
__device__ __align__(1024) float g_gT[DD * NN];
__device__ __align__(128)  float g_d[NN];
__device__ __align__(128)  float g_e[NN];

// ============================================================================
// PTX helpers
// ============================================================================
__device__ __forceinline__ uint32_t smem_u32(const void* p) {
    uint32_t a;
    asm("{ .reg .u64 t; cvta.to.shared.u64 t, %1; cvt.u32.u64 %0, t; }" : "=r"(a) : "l"(p));
    return a;
}

__device__ __forceinline__ void cp16(uint32_t dst, const void* src) {
    asm volatile("cp.async.cg.shared.global [%0], [%1], 16;" :: "r"(dst), "l"(src));
}

#define CP_COMMIT()  asm volatile("cp.async.commit_group;" ::: "memory")
#define CP_WAIT(n)   asm volatile("cp.async.wait_group %0;" :: "n"(n) : "memory")

__device__ __forceinline__ void mma_tf32(float* c, const uint32_t* a, const uint32_t* b) {
    asm volatile(
        "mma.sync.aligned.m16n8k8.row.col.f32.tf32.tf32.f32 "
        "{%0,%1,%2,%3}, {%4,%5,%6,%7}, {%8,%9}, {%0,%1,%2,%3};"
        : "+f"(c[0]), "+f"(c[1]), "+f"(c[2]), "+f"(c[3])
        : "r"(a[0]), "r"(a[1]), "r"(a[2]), "r"(a[3]), "r"(b[0]), "r"(b[1]));
}

// ============================================================================
// K1: h = x @ W + b   (8192x128 @ 128x128)
// ============================================================================
__global__ void __launch_bounds__(128) xw_kernel(const float* __restrict__ x,
                                                 const float* __restrict__ W,
                                                 const float* __restrict__ bias) {
    __shared__ float xs[32][128];
    const int r0 = blockIdx.x * 32;
    const int tid = threadIdx.x;

    const float4* xsrc = (const float4*)(x + (size_t)r0 * DD);
    float4* xdst = (float4*)&xs[0][0];
    for (int idx = tid; idx < 32 * 32; idx += 128) xdst[idx] = xsrc[idx];
    __syncthreads();

    const int n = tid;
    const float b = bias[n];
    float acc[32];
#pragma unroll
    for (int r = 0; r < 32; r++) acc[r] = b;

    for (int k = 0; k < 128; k++) {
        float w = W[k * DD + n];
#pragma unroll
        for (int r = 0; r < 32; r++) acc[r] = fmaf(xs[r][k], w, acc[r]);
    }
#pragma unroll
    for (int r = 0; r < 32; r++) g_h[(size_t)(r0 + r) * DD + n] = acc[r];
}

// ============================================================================
// K2: rowsum(A) with self-loop -> d, e   (one block per row)
// ============================================================================
__global__ void __launch_bounds__(256) rowsum_kernel(const float* __restrict__ A) {
    const int i = blockIdx.x;
    const int tid = threadIdx.x;
    const float4* row = (const float4*)(A + (size_t)i * NN);
    float s = 0.f;
#pragma unroll 4
    for (int c = tid; c < NN / 4; c += 256) {
        float4 v = row[c];
        s += (v.x + v.y) + (v.z + v.w);
    }
#pragma unroll
    for (int o = 16; o; o >>= 1) s += __shfl_down_sync(0xffffffffu, s, o);
    __shared__ float red[8];
    if ((tid & 31) == 0) red[tid >> 5] = s;
    __syncthreads();
    if (tid == 0) {
        float tot = 0.f;
#pragma unroll
        for (int w = 0; w < 8; w++) tot += red[w];
        float aii = A[(size_t)i * NN + i];
        tot = tot - aii + 1.0f;           // exact: small-integer arithmetic in f32
        float di = rsqrtf(tot);
        g_d[i] = di;
        g_e[i] = di * (1.0f - aii);
    }
}

// ============================================================================
// K3: g = D*h (fp32) and gT = tf32_rna(g)^T  (GEMM B operand, 128 x 8192)
// ============================================================================
__global__ void __launch_bounds__(256) scale_transpose_kernel() {
    __shared__ float t[32][33];
    const int i0 = blockIdx.x * 32;
    const int n0 = blockIdx.y * 32;
    const int tx = threadIdx.x, ty = threadIdx.y;

    for (int r = ty; r < 32; r += 8) {
        int i = i0 + r;
        float v = g_h[(size_t)i * DD + n0 + tx] * g_d[i];
        g_g[(size_t)i * DD + n0 + tx] = v;
        t[r][tx] = v;
    }
    __syncthreads();
    for (int r = ty; r < 32; r += 8) {
        float v = t[tx][r];                       // element (row i0+tx, col n0+r)
        uint32_t tf;
        asm("cvt.rna.tf32.f32 %0, %1;" : "=r"(tf) : "f"(v));
        g_gT[(size_t)(n0 + r) * NN + i0 + tx] = __uint_as_float(tf);
    }
}

// ============================================================================
// K4: out = D * (A @ g) + diag(e) * g
//   tf32 mma.sync GEMM: CTA tile 64x128, 16 warps (4m x 4n), warp tile 16x32,
//   BK=32, 5-stage cp.async pipeline.
// ============================================================================
__global__ void __launch_bounds__(GTHREADS, 1) gcn_gemm(
    const float* __restrict__ A, float* __restrict__ out)
{
    extern __shared__ float smem[];
    const int tid = threadIdx.x;
    const int wid = tid >> 5;
    const int lane = tid & 31;
    const int gid = lane >> 2;     // group id 0..7
    const int tg  = lane & 3;      // thread-in-group 0..3
    const int m0 = blockIdx.x * BM;

    const int wm = wid & 3;        // 4 warps along M
    const int wn = wid >> 2;       // 4 warps along N
    const int mwb = wm * 16;       // warp m-offset in tile
    const int nwb = wn * 32;       // warp n-offset in tile

    const uint32_t smem_base = smem_u32(smem);

    // ---------------- cp.async stage fill ----------------
    // 1536 chunks of 16B per stage: A = 512 (64 rows x 8), B = 1024 (128 x 8)
    auto issue_stage = [&](int kt, int slot) {
        const int k0 = kt * BK;
        const uint32_t sA = smem_base + (uint32_t)(slot * STAGE_FLOATS) * 4u;
        const uint32_t sB = sA + AS_FLOATS * 4u;
#pragma unroll
        for (int j = 0; j < 3; j++) {
            int c = tid + j * GTHREADS;
            if (c < 512) {
                int r = c >> 3, c8 = c & 7;
                cp16(sA + (uint32_t)(r * APAD + c8 * 4) * 4u,
                     A + (size_t)(m0 + r) * NN + k0 + c8 * 4);
            } else {
                int cb = c - 512;
                int r = cb >> 3, c8 = cb & 7;
                cp16(sB + (uint32_t)(r * APAD + c8 * 4) * 4u,
                     g_gT + (size_t)r * NN + k0 + c8 * 4);
            }
        }
    };

    float c[4][4];                 // [nf][quad] warp tile 16x32
#pragma unroll
    for (int nf = 0; nf < 4; nf++)
#pragma unroll
        for (int q = 0; q < 4; q++) c[nf][q] = 0.f;

    // prefetch first STAGES-1 stages
#pragma unroll
    for (int s = 0; s < STAGES - 1; s++) {
        issue_stage(s, s);
        CP_COMMIT();
    }

    // per-thread base offsets within a stage (in floats)
    const int a_r0 = (mwb + gid) * APAD + tg;
    const int a_r1 = (mwb + 8 + gid) * APAD + tg;
    const int b_r0 = (nwb + gid) * APAD + tg;
    const int b_r1 = (nwb + 8 + gid) * APAD + tg;
    const int b_r2 = (nwb + 16 + gid) * APAD + tg;
    const int b_r3 = (nwb + 24 + gid) * APAD + tg;

    int slot_r = 0;
    int slot_w = STAGES - 1;

    for (int kt = 0; kt < NKT; kt++) {
        CP_WAIT(STAGES - 2);
        __syncthreads();

        int nxt = kt + STAGES - 1;
        if (nxt < NKT) issue_stage(nxt, slot_w);
        CP_COMMIT();
        if (++slot_w == STAGES) slot_w = 0;

        const uint32_t* sA = (const uint32_t*)(smem + slot_r * STAGE_FLOATS);
        const uint32_t* sB = sA + AS_FLOATS;
        if (++slot_r == STAGES) slot_r = 0;

#pragma unroll
        for (int kk = 0; kk < 4; kk++) {
            const int k = kk * 8;
            uint32_t a[4], b[4][2];
            a[0] = sA[a_r0 + k];
            a[1] = sA[a_r1 + k];
            a[2] = sA[a_r0 + k + 4];
            a[3] = sA[a_r1 + k + 4];
            b[0][0] = sB[b_r0 + k]; b[0][1] = sB[b_r0 + k + 4];
            b[1][0] = sB[b_r1 + k]; b[1][1] = sB[b_r1 + k + 4];
            b[2][0] = sB[b_r2 + k]; b[2][1] = sB[b_r2 + k + 4];
            b[3][0] = sB[b_r3 + k]; b[3][1] = sB[b_r3 + k + 4];
#pragma unroll
            for (int nf = 0; nf < 4; nf++)
                mma_tf32(c[nf], a, b[nf]);
        }
    }

    // ---------------- epilogue ----------------
    {
        int i0r = m0 + mwb + gid;
        int i1r = i0r + 8;
        float d0 = g_d[i0r], e0 = g_e[i0r];
        float d1 = g_d[i1r], e1 = g_e[i1r];
#pragma unroll
        for (int nf = 0; nf < 4; nf++) {
            int n = nwb + nf * 8 + tg * 2;
            const float2 gv0 = *(const float2*)(g_g + (size_t)i0r * DD + n);
            const float2 gv1 = *(const float2*)(g_g + (size_t)i1r * DD + n);
            float2 o0, o1;
            o0.x = d0 * c[nf][0] + e0 * gv0.x;
            o0.y = d0 * c[nf][1] + e0 * gv0.y;
            o1.x = d1 * c[nf][2] + e1 * gv1.x;
            o1.y = d1 * c[nf][3] + e1 * gv1.y;
            *(float2*)(out + (size_t)i0r * DD + n) = o0;
            *(float2*)(out + (size_t)i1r * DD + n) = o1;
        }
    }
}

// ============================================================================
// Host side
// ============================================================================
extern "C" void kernel_launch(void* const* d_in, const int* in_sizes, int n_in,
                              void* d_out, int out_size) {
    const float* A    = (const float*)d_in[0];
    const float* x    = (const float*)d_in[1];
    const float* W    = (const float*)d_in[2];
    const float* bias = (const float*)d_in[3];
    float* out = (float*)d_out;

    cudaFuncSetAttribute(gcn_gemm, cudaFuncAttributeMaxDynamicSharedMemorySize, SMEM_TOTAL);

    xw_kernel<<<NN / 32, 128>>>(x, W, bias);
    rowsum_kernel<<<NN, 256>>>(A);
    scale_transpose_kernel<<<dim3(NN / 32, DD / 32), dim3(32, 8)>>>();
    gcn_gemm<<<NN / BM, GTHREADS, SMEM_TOTAL>>>(A, out);
}

// round 6
// speedup vs baseline: 1.2019x; 1.2019x over previous
#include <cuda_runtime.h>
#include <cuda.h>
#include <cstdint>

// ============================================================================
// Problem constants
// ============================================================================
#define NN      8192
#define DD      128

// GEMM config (Ampere-style mma.sync tf32 + ldmatrix; baseline PTX for sm_100)
#define BM      64
#define BN      128
#define BK      32
#define STAGES  5
#define NKT     (NN / BK)      // 256 K iterations
#define GTHREADS 256           // 8 warps: 2 along M x 4 along N, warp tile 32x32

// SMEM tile strides (floats); +4 pad keeps LDS/ldmatrix conflict-free
#define APAD    36             // 32 + 4
#define AS_FLOATS (BM * APAD)          // 2304
#define BS_FLOATS (BN * APAD)          // 4608
#define STAGE_FLOATS (AS_FLOATS + BS_FLOATS)   // 6912
#define SMEM_TOTAL (STAGES * STAGE_FLOATS * 4) // 138240 bytes

// ============================================================================
// Scratch (device globals; allocation-free)
// ============================================================================
__device__ __align__(1024) float g_h[NN * DD];
__device__ __align__(1024) float g_g[NN * DD];
__device__ __align__(1024) float g_gT[DD * NN];
__device__ __align__(128)  float g_d[NN];
__device__ __align__(128)  float g_e[NN];

// ============================================================================
// PTX helpers
// ============================================================================
__device__ __forceinline__ uint32_t smem_u32(const void* p) {
    uint32_t a;
    asm("{ .reg .u64 t; cvta.to.shared.u64 t, %1; cvt.u32.u64 %0, t; }" : "=r"(a) : "l"(p));
    return a;
}

__device__ __forceinline__ void cp16(uint32_t dst, const void* src) {
    asm volatile("cp.async.cg.shared.global [%0], [%1], 16;" :: "r"(dst), "l"(src));
}

#define CP_COMMIT()  asm volatile("cp.async.commit_group;" ::: "memory")
#define CP_WAIT(n)   asm volatile("cp.async.wait_group %0;" :: "n"(n) : "memory")

// ldmatrix x4: each 32-bit lane word = one tf32 element; tile = 8 rows x 16B
__device__ __forceinline__ void ldsm_x4(uint32_t* r, uint32_t addr) {
    asm volatile("ldmatrix.sync.aligned.m8n8.x4.shared.b16 {%0,%1,%2,%3}, [%4];"
                 : "=r"(r[0]), "=r"(r[1]), "=r"(r[2]), "=r"(r[3]) : "r"(addr));
}

__device__ __forceinline__ void mma_tf32(float* c, const uint32_t* a, const uint32_t* b) {
    asm volatile(
        "mma.sync.aligned.m16n8k8.row.col.f32.tf32.tf32.f32 "
        "{%0,%1,%2,%3}, {%4,%5,%6,%7}, {%8,%9}, {%0,%1,%2,%3};"
        : "+f"(c[0]), "+f"(c[1]), "+f"(c[2]), "+f"(c[3])
        : "r"(a[0]), "r"(a[1]), "r"(a[2]), "r"(a[3]), "r"(b[0]), "r"(b[1]));
}

// ============================================================================
// K1 (fused): blocks 0..255 -> h = x @ W + b ; blocks 256.. -> rowsum(A)
// ============================================================================
__global__ void __launch_bounds__(256) pre_kernel(const float* __restrict__ A,
                                                  const float* __restrict__ x,
                                                  const float* __restrict__ W,
                                                  const float* __restrict__ bias) {
    __shared__ float xs[32][128];
    __shared__ float red[8];
    const int tid = threadIdx.x;

    if (blockIdx.x < 256) {
        // ---------------- x @ W + b : 32 rows per block ----------------
        const int r0 = blockIdx.x * 32;
        const float4* xsrc = (const float4*)(x + (size_t)r0 * DD);
        float4* xdst = (float4*)&xs[0][0];
        for (int idx = tid; idx < 32 * 32; idx += 256) xdst[idx] = xsrc[idx];
        __syncthreads();

        const int n = tid & 127;
        const int rbase = (tid >> 7) * 16;
        const float b = bias[n];
        float acc[16];
#pragma unroll
        for (int r = 0; r < 16; r++) acc[r] = b;
        for (int k = 0; k < 128; k++) {
            float w = W[k * DD + n];
#pragma unroll
            for (int r = 0; r < 16; r++) acc[r] = fmaf(xs[rbase + r][k], w, acc[r]);
        }
#pragma unroll
        for (int r = 0; r < 16; r++) g_h[(size_t)(r0 + rbase + r) * DD + n] = acc[r];
    } else {
        // ---------------- rowsum(A) with self-loop -> d, e ----------------
        const int i = blockIdx.x - 256;
        const float4* row = (const float4*)(A + (size_t)i * NN);
        float s = 0.f;
#pragma unroll 4
        for (int c = tid; c < NN / 4; c += 256) {
            float4 v = row[c];
            s += (v.x + v.y) + (v.z + v.w);
        }
#pragma unroll
        for (int o = 16; o; o >>= 1) s += __shfl_down_sync(0xffffffffu, s, o);
        if ((tid & 31) == 0) red[tid >> 5] = s;
        __syncthreads();
        if (tid == 0) {
            float tot = 0.f;
#pragma unroll
            for (int w = 0; w < 8; w++) tot += red[w];
            float aii = A[(size_t)i * NN + i];
            tot = tot - aii + 1.0f;       // exact small-integer arithmetic
            float di = rsqrtf(tot);
            g_d[i] = di;
            g_e[i] = di * (1.0f - aii);
        }
    }
}

// ============================================================================
// K2: g = D*h (fp32) and gT = tf32_rna(g)^T  (GEMM B operand, 128 x 8192)
// ============================================================================
__global__ void __launch_bounds__(256) scale_transpose_kernel() {
    __shared__ float t[32][33];
    const int i0 = blockIdx.x * 32;
    const int n0 = blockIdx.y * 32;
    const int tx = threadIdx.x, ty = threadIdx.y;

    for (int r = ty; r < 32; r += 8) {
        int i = i0 + r;
        float v = g_h[(size_t)i * DD + n0 + tx] * g_d[i];
        g_g[(size_t)i * DD + n0 + tx] = v;
        t[r][tx] = v;
    }
    __syncthreads();
    for (int r = ty; r < 32; r += 8) {
        float v = t[tx][r];                       // element (row i0+tx, col n0+r)
        uint32_t tf;
        asm("cvt.rna.tf32.f32 %0, %1;" : "=r"(tf) : "f"(v));
        g_gT[(size_t)(n0 + r) * NN + i0 + tx] = __uint_as_float(tf);
    }
}

// ============================================================================
// K3: out = D * (A @ g) + diag(e) * g
//   tf32 mma.sync GEMM: CTA tile 64x128, 8 warps (2m x 4n), warp tile 32x32,
//   BK=32, 5-stage cp.async pipeline, ldmatrix.x4 fragment loads.
// ============================================================================
__global__ void __launch_bounds__(GTHREADS, 1) gcn_gemm(
    const float* __restrict__ A, float* __restrict__ out)
{
    extern __shared__ float smem[];
    const int tid = threadIdx.x;
    const int wid = tid >> 5;
    const int lane = tid & 31;
    const int gid = lane >> 2;     // group id 0..7
    const int tg  = lane & 3;      // thread-in-group 0..3
    const int m0 = blockIdx.x * BM;

    const int wm = wid & 1;        // 2 warps along M
    const int wn = wid >> 1;       // 4 warps along N
    const int mwb = wm * 32;       // warp m-offset in tile
    const int nwb = wn * 32;       // warp n-offset in tile

    const uint32_t smem_base = smem_u32(smem);

    // ldmatrix per-lane source addressing (bytes, relative to tile base)
    const int l7  = lane & 7;
    const int l8  = (lane >> 3) & 1;
    const int l16 = (lane >> 4) & 1;
    // A tiles: rows mwb + mf*16 + l7 + l8*8, k-word offset l16*4 floats
    const uint32_t a_off0 = (uint32_t)(((mwb + l7 + l8 * 8) * APAD + l16 * 4) * 4);
    const uint32_t a_off1 = a_off0 + 16u * APAD * 4u;
    // B tiles: rows nwb + l16*8 + l7, k-word offset l8*4 floats
    const uint32_t b_off0 = (uint32_t)(((nwb + l16 * 8 + l7) * APAD + l8 * 4) * 4);
    const uint32_t b_off1 = b_off0 + 16u * APAD * 4u;

    // ---------------- cp.async stage fill ----------------
    // 1536 chunks of 16B per stage: A = 512 (64 rows x 8), B = 1024 (128 x 8)
    auto issue_stage = [&](int kt, int slot) {
        const int k0 = kt * BK;
        const uint32_t sA = smem_base + (uint32_t)(slot * STAGE_FLOATS) * 4u;
        const uint32_t sB = sA + AS_FLOATS * 4u;
#pragma unroll
        for (int j = 0; j < 6; j++) {
            int c = tid + j * GTHREADS;
            if (c < 512) {
                int r = c >> 3, c8 = c & 7;
                cp16(sA + (uint32_t)(r * APAD + c8 * 4) * 4u,
                     A + (size_t)(m0 + r) * NN + k0 + c8 * 4);
            } else {
                int cb = c - 512;
                int r = cb >> 3, c8 = cb & 7;
                cp16(sB + (uint32_t)(r * APAD + c8 * 4) * 4u,
                     g_gT + (size_t)r * NN + k0 + c8 * 4);
            }
        }
    };

    float c[2][4][4];
#pragma unroll
    for (int mf = 0; mf < 2; mf++)
#pragma unroll
        for (int nf = 0; nf < 4; nf++)
#pragma unroll
            for (int q = 0; q < 4; q++) c[mf][nf][q] = 0.f;

    // prefetch first STAGES-1 stages
#pragma unroll
    for (int s = 0; s < STAGES - 1; s++) {
        issue_stage(s, s);
        CP_COMMIT();
    }

    int slot_r = 0;
    int slot_w = STAGES - 1;

    for (int kt = 0; kt < NKT; kt++) {
        CP_WAIT(STAGES - 2);
        __syncthreads();

        int nxt = kt + STAGES - 1;
        if (nxt < NKT) issue_stage(nxt, slot_w);
        CP_COMMIT();
        if (++slot_w == STAGES) slot_w = 0;

        const uint32_t aB = smem_base + (uint32_t)(slot_r * STAGE_FLOATS) * 4u;
        const uint32_t bB = aB + AS_FLOATS * 4u;
        if (++slot_r == STAGES) slot_r = 0;

#pragma unroll
        for (int kk = 0; kk < 4; kk++) {
            const uint32_t ko = (uint32_t)kk * 32u;   // 8 floats = 32 bytes
            uint32_t a0[4], a1[4], b0[4], b1[4];
            ldsm_x4(a0, aB + a_off0 + ko);            // a[mf=0]
            ldsm_x4(a1, aB + a_off1 + ko);            // a[mf=1]
            ldsm_x4(b0, bB + b_off0 + ko);            // {b[nf0][0..1], b[nf1][0..1]}
            ldsm_x4(b1, bB + b_off1 + ko);            // {b[nf2][0..1], b[nf3][0..1]}
            mma_tf32(c[0][0], a0, b0);
            mma_tf32(c[0][1], a0, b0 + 2);
            mma_tf32(c[0][2], a0, b1);
            mma_tf32(c[0][3], a0, b1 + 2);
            mma_tf32(c[1][0], a1, b0);
            mma_tf32(c[1][1], a1, b0 + 2);
            mma_tf32(c[1][2], a1, b1);
            mma_tf32(c[1][3], a1, b1 + 2);
        }
    }

    // ---------------- epilogue ----------------
#pragma unroll
    for (int mf = 0; mf < 2; mf++) {
        int i0r = m0 + mwb + mf * 16 + gid;
        int i1r = i0r + 8;
        float d0 = g_d[i0r], e0 = g_e[i0r];
        float d1 = g_d[i1r], e1 = g_e[i1r];
#pragma unroll
        for (int nf = 0; nf < 4; nf++) {
            int n = nwb + nf * 8 + tg * 2;
            const float2 gv0 = *(const float2*)(g_g + (size_t)i0r * DD + n);
            const float2 gv1 = *(const float2*)(g_g + (size_t)i1r * DD + n);
            float2 o0, o1;
            o0.x = d0 * c[mf][nf][0] + e0 * gv0.x;
            o0.y = d0 * c[mf][nf][1] + e0 * gv0.y;
            o1.x = d1 * c[mf][nf][2] + e1 * gv1.x;
            o1.y = d1 * c[mf][nf][3] + e1 * gv1.y;
            *(float2*)(out + (size_t)i0r * DD + n) = o0;
            *(float2*)(out + (size_t)i1r * DD + n) = o1;
        }
    }
}

// ============================================================================
// Host side
// ============================================================================
extern "C" void kernel_launch(void* const* d_in, const int* in_sizes, int n_in,
                              void* d_out, int out_size) {
    const float* A    = (const float*)d_in[0];
    const float* x    = (const float*)d_in[1];
    const float* W    = (const float*)d_in[2];
    const float* bias = (const float*)d_in[3];
    float* out = (float*)d_out;

    cudaFuncSetAttribute(gcn_gemm, cudaFuncAttributeMaxDynamicSharedMemorySize, SMEM_TOTAL);

    pre_kernel<<<NN + 256, 256>>>(A, x, W, bias);
    scale_transpose_kernel<<<dim3(NN / 32, DD / 32), dim3(32, 8)>>>();
    gcn_gemm<<<NN / BM, GTHREADS, SMEM_TOTAL>>>(A, out);
}

// round 7
// speedup vs baseline: 1.3107x; 1.0906x over previous
#include <cuda_runtime.h>
#include <cuda.h>
#include <cstdint>

// ============================================================================
// Problem constants
// ============================================================================
#define NN      8192
#define DD      128

// GEMM config (Ampere-style mma.sync tf32 + ldmatrix; baseline PTX for sm_100)
#define BM      64
#define BN      128
#define BK      32
#define STAGES  4
#define KSPLIT  2
#define KHALF   (NN / KSPLIT)          // 4096
#define NKT     (KHALF / BK)           // 128 K iterations per CTA
#define GTHREADS 256                   // 8 warps: 2 along M x 4 along N

// SMEM tile strides (floats); +4 pad keeps LDS/ldmatrix conflict-free
#define APAD    36             // 32 + 4
#define AS_FLOATS (BM * APAD)          // 2304
#define BS_FLOATS (BN * APAD)          // 4608
#define STAGE_FLOATS (AS_FLOATS + BS_FLOATS)   // 6912
#define SMEM_TOTAL (STAGES * STAGE_FLOATS * 4) // 110592 bytes -> 2 CTAs/SM

// ============================================================================
// Scratch (device globals; allocation-free)
// ============================================================================
__device__ __align__(1024) float g_h[NN * DD];
__device__ __align__(1024) float g_g[NN * DD];
__device__ __align__(1024) float g_gT[DD * NN];
__device__ __align__(1024) float g_p[KSPLIT][NN * DD];
__device__ __align__(128)  float g_d[NN];
__device__ __align__(128)  float g_e[NN];

// ============================================================================
// PTX helpers
// ============================================================================
__device__ __forceinline__ uint32_t smem_u32(const void* p) {
    uint32_t a;
    asm("{ .reg .u64 t; cvta.to.shared.u64 t, %1; cvt.u32.u64 %0, t; }" : "=r"(a) : "l"(p));
    return a;
}

__device__ __forceinline__ void cp16(uint32_t dst, const void* src) {
    asm volatile("cp.async.cg.shared.global [%0], [%1], 16;" :: "r"(dst), "l"(src));
}

#define CP_COMMIT()  asm volatile("cp.async.commit_group;" ::: "memory")
#define CP_WAIT(n)   asm volatile("cp.async.wait_group %0;" :: "n"(n) : "memory")

// ldmatrix x4: each 32-bit lane word = one tf32 element; tile = 8 rows x 16B
__device__ __forceinline__ void ldsm_x4(uint32_t* r, uint32_t addr) {
    asm volatile("ldmatrix.sync.aligned.m8n8.x4.shared.b16 {%0,%1,%2,%3}, [%4];"
                 : "=r"(r[0]), "=r"(r[1]), "=r"(r[2]), "=r"(r[3]) : "r"(addr));
}

__device__ __forceinline__ void mma_tf32(float* c, const uint32_t* a, const uint32_t* b) {
    asm volatile(
        "mma.sync.aligned.m16n8k8.row.col.f32.tf32.tf32.f32 "
        "{%0,%1,%2,%3}, {%4,%5,%6,%7}, {%8,%9}, {%0,%1,%2,%3};"
        : "+f"(c[0]), "+f"(c[1]), "+f"(c[2]), "+f"(c[3])
        : "r"(a[0]), "r"(a[1]), "r"(a[2]), "r"(a[3]), "r"(b[0]), "r"(b[1]));
}

// ============================================================================
// K1 (fused): blocks 0..255 -> h = x @ W + b ; blocks 256.. -> rowsum(A)
// ============================================================================
__global__ void __launch_bounds__(256) pre_kernel(const float* __restrict__ A,
                                                  const float* __restrict__ x,
                                                  const float* __restrict__ W,
                                                  const float* __restrict__ bias) {
    __shared__ float xs[32][128];
    __shared__ float red[8];
    const int tid = threadIdx.x;

    if (blockIdx.x < 256) {
        // ---------------- x @ W + b : 32 rows per block ----------------
        const int r0 = blockIdx.x * 32;
        const float4* xsrc = (const float4*)(x + (size_t)r0 * DD);
        float4* xdst = (float4*)&xs[0][0];
        for (int idx = tid; idx < 32 * 32; idx += 256) xdst[idx] = xsrc[idx];
        __syncthreads();

        const int n = tid & 127;
        const int rbase = (tid >> 7) * 16;
        const float b = bias[n];
        float acc[16];
#pragma unroll
        for (int r = 0; r < 16; r++) acc[r] = b;
        for (int k = 0; k < 128; k++) {
            float w = W[k * DD + n];
#pragma unroll
            for (int r = 0; r < 16; r++) acc[r] = fmaf(xs[rbase + r][k], w, acc[r]);
        }
#pragma unroll
        for (int r = 0; r < 16; r++) g_h[(size_t)(r0 + rbase + r) * DD + n] = acc[r];
    } else {
        // ---------------- rowsum(A) with self-loop -> d, e ----------------
        const int i = blockIdx.x - 256;
        const float4* row = (const float4*)(A + (size_t)i * NN);
        float s = 0.f;
#pragma unroll 4
        for (int c = tid; c < NN / 4; c += 256) {
            float4 v = row[c];
            s += (v.x + v.y) + (v.z + v.w);
        }
#pragma unroll
        for (int o = 16; o; o >>= 1) s += __shfl_down_sync(0xffffffffu, s, o);
        if ((tid & 31) == 0) red[tid >> 5] = s;
        __syncthreads();
        if (tid == 0) {
            float tot = 0.f;
#pragma unroll
            for (int w = 0; w < 8; w++) tot += red[w];
            float aii = A[(size_t)i * NN + i];
            tot = tot - aii + 1.0f;       // exact small-integer arithmetic
            float di = rsqrtf(tot);
            g_d[i] = di;
            g_e[i] = di * (1.0f - aii);
        }
    }
}

// ============================================================================
// K2: g = D*h (fp32) and gT = tf32_rna(g)^T  (GEMM B operand, 128 x 8192)
// ============================================================================
__global__ void __launch_bounds__(256) scale_transpose_kernel() {
    __shared__ float t[32][33];
    const int i0 = blockIdx.x * 32;
    const int n0 = blockIdx.y * 32;
    const int tx = threadIdx.x, ty = threadIdx.y;

    for (int r = ty; r < 32; r += 8) {
        int i = i0 + r;
        float v = g_h[(size_t)i * DD + n0 + tx] * g_d[i];
        g_g[(size_t)i * DD + n0 + tx] = v;
        t[r][tx] = v;
    }
    __syncthreads();
    for (int r = ty; r < 32; r += 8) {
        float v = t[tx][r];                       // element (row i0+tx, col n0+r)
        uint32_t tf;
        asm("cvt.rna.tf32.f32 %0, %1;" : "=r"(tf) : "f"(v));
        g_gT[(size_t)(n0 + r) * NN + i0 + tx] = __uint_as_float(tf);
    }
}

// ============================================================================
// K3: partial = A[:, ksplit] @ g[ksplit]  (split-K tf32 mma.sync GEMM)
//   CTA tile 64x128, 8 warps (2m x 4n), warp tile 32x32, BK=32,
//   4-stage cp.async pipeline, ldmatrix.x4 loads, 2 CTAs/SM.
// ============================================================================
__global__ void __launch_bounds__(GTHREADS, 2) gcn_gemm(const float* __restrict__ A)
{
    extern __shared__ float smem[];
    const int tid = threadIdx.x;
    const int wid = tid >> 5;
    const int lane = tid & 31;
    const int gid = lane >> 2;
    const int tg  = lane & 3;
    const int m0 = blockIdx.x * BM;
    const int split = blockIdx.y;
    const int kbase = split * KHALF;
    float* __restrict__ part = g_p[split];

    const int wm = wid & 1;
    const int wn = wid >> 1;
    const int mwb = wm * 32;
    const int nwb = wn * 32;

    const uint32_t smem_base = smem_u32(smem);

    const int l7  = lane & 7;
    const int l8  = (lane >> 3) & 1;
    const int l16 = (lane >> 4) & 1;
    const uint32_t a_off0 = (uint32_t)(((mwb + l7 + l8 * 8) * APAD + l16 * 4) * 4);
    const uint32_t a_off1 = a_off0 + 16u * APAD * 4u;
    const uint32_t b_off0 = (uint32_t)(((nwb + l16 * 8 + l7) * APAD + l8 * 4) * 4);
    const uint32_t b_off1 = b_off0 + 16u * APAD * 4u;

    auto issue_stage = [&](int kt, int slot) {
        const int k0 = kbase + kt * BK;
        const uint32_t sA = smem_base + (uint32_t)(slot * STAGE_FLOATS) * 4u;
        const uint32_t sB = sA + AS_FLOATS * 4u;
#pragma unroll
        for (int j = 0; j < 6; j++) {
            int c = tid + j * GTHREADS;
            if (c < 512) {
                int r = c >> 3, c8 = c & 7;
                cp16(sA + (uint32_t)(r * APAD + c8 * 4) * 4u,
                     A + (size_t)(m0 + r) * NN + k0 + c8 * 4);
            } else {
                int cb = c - 512;
                int r = cb >> 3, c8 = cb & 7;
                cp16(sB + (uint32_t)(r * APAD + c8 * 4) * 4u,
                     g_gT + (size_t)r * NN + k0 + c8 * 4);
            }
        }
    };

    float c[2][4][4];
#pragma unroll
    for (int mf = 0; mf < 2; mf++)
#pragma unroll
        for (int nf = 0; nf < 4; nf++)
#pragma unroll
            for (int q = 0; q < 4; q++) c[mf][nf][q] = 0.f;

#pragma unroll
    for (int s = 0; s < STAGES - 1; s++) {
        issue_stage(s, s);
        CP_COMMIT();
    }

    int slot_r = 0;
    int slot_w = STAGES - 1;

    for (int kt = 0; kt < NKT; kt++) {
        CP_WAIT(STAGES - 2);
        __syncthreads();

        int nxt = kt + STAGES - 1;
        if (nxt < NKT) issue_stage(nxt, slot_w);
        CP_COMMIT();
        if (++slot_w == STAGES) slot_w = 0;

        const uint32_t aB = smem_base + (uint32_t)(slot_r * STAGE_FLOATS) * 4u;
        const uint32_t bB = aB + AS_FLOATS * 4u;
        if (++slot_r == STAGES) slot_r = 0;

#pragma unroll
        for (int kk = 0; kk < 4; kk++) {
            const uint32_t ko = (uint32_t)kk * 32u;
            uint32_t a0[4], a1[4], b0[4], b1[4];
            ldsm_x4(a0, aB + a_off0 + ko);
            ldsm_x4(a1, aB + a_off1 + ko);
            ldsm_x4(b0, bB + b_off0 + ko);
            ldsm_x4(b1, bB + b_off1 + ko);
            mma_tf32(c[0][0], a0, b0);
            mma_tf32(c[0][1], a0, b0 + 2);
            mma_tf32(c[0][2], a0, b1);
            mma_tf32(c[0][3], a0, b1 + 2);
            mma_tf32(c[1][0], a1, b0);
            mma_tf32(c[1][1], a1, b0 + 2);
            mma_tf32(c[1][2], a1, b1);
            mma_tf32(c[1][3], a1, b1 + 2);
        }
    }

    // ---------------- epilogue: raw partial store ----------------
#pragma unroll
    for (int mf = 0; mf < 2; mf++) {
        int i0r = m0 + mwb + mf * 16 + gid;
        int i1r = i0r + 8;
#pragma unroll
        for (int nf = 0; nf < 4; nf++) {
            int n = nwb + nf * 8 + tg * 2;
            *(float2*)(part + (size_t)i0r * DD + n) = make_float2(c[mf][nf][0], c[mf][nf][1]);
            *(float2*)(part + (size_t)i1r * DD + n) = make_float2(c[mf][nf][2], c[mf][nf][3]);
        }
    }
}

// ============================================================================
// K4: out = d * (p0 + p1) + e * g
// ============================================================================
__global__ void __launch_bounds__(256) combine_kernel(float* __restrict__ out) {
    const int idx = blockIdx.x * 256 + threadIdx.x;      // float4 index
    const int i = (idx * 4) / DD;
    const float d = g_d[i], e = g_e[i];
    const float4 p0 = ((const float4*)g_p[0])[idx];
    const float4 p1 = ((const float4*)g_p[1])[idx];
    const float4 gv = ((const float4*)g_g)[idx];
    float4 o;
    o.x = d * (p0.x + p1.x) + e * gv.x;
    o.y = d * (p0.y + p1.y) + e * gv.y;
    o.z = d * (p0.z + p1.z) + e * gv.z;
    o.w = d * (p0.w + p1.w) + e * gv.w;
    ((float4*)out)[idx] = o;
}

// ============================================================================
// Host side
// ============================================================================
extern "C" void kernel_launch(void* const* d_in, const int* in_sizes, int n_in,
                              void* d_out, int out_size) {
    const float* A    = (const float*)d_in[0];
    const float* x    = (const float*)d_in[1];
    const float* W    = (const float*)d_in[2];
    const float* bias = (const float*)d_in[3];
    float* out = (float*)d_out;

    cudaFuncSetAttribute(gcn_gemm, cudaFuncAttributeMaxDynamicSharedMemorySize, SMEM_TOTAL);

    pre_kernel<<<NN + 256, 256>>>(A, x, W, bias);
    scale_transpose_kernel<<<dim3(NN / 32, DD / 32), dim3(32, 8)>>>();
    gcn_gemm<<<dim3(NN / BM, KSPLIT), GTHREADS, SMEM_TOTAL>>>(A);
    combine_kernel<<<(NN * DD / 4) / 256, 256>>>(out);
}

// round 8
// speedup vs baseline: 1.4873x; 1.1347x over previous
#include <cuda_runtime.h>
#include <cuda.h>
#include <cstdint>

// ============================================================================
// Problem constants
// ============================================================================
#define NN      8192
#define DD      128

// GEMM config: CTA tile 256x128, 16 warps (8m x 2n), warp tile 32x64
#define BM      256
#define BN      128
#define BK      32
#define STAGES  4
#define KSPLIT  8
#define KCHUNK  (NN / KSPLIT)          // 1024
#define NKT     (KCHUNK / BK)          // 32 K iterations per CTA
#define GTHREADS 512                   // 16 warps

// SMEM tile strides (floats); +4 pad keeps ldmatrix conflict-free
#define APAD    36             // 32 + 4
#define AS_FLOATS (BM * APAD)          // 9216
#define BS_FLOATS (BN * APAD)          // 4608
#define STAGE_FLOATS (AS_FLOATS + BS_FLOATS)   // 13824
#define SMEM_TOTAL (STAGES * STAGE_FLOATS * 4) // 221184 bytes (1 CTA/SM)

// ============================================================================
// Scratch (device globals; allocation-free)
// ============================================================================
__device__ __align__(1024) float g_h[NN * DD];
__device__ __align__(1024) float g_g[NN * DD];
__device__ __align__(1024) float g_gT[DD * NN];
__device__ __align__(1024) float g_p[KSPLIT][NN * DD];
__device__ __align__(128)  float g_d[NN];
__device__ __align__(128)  float g_e[NN];

// ============================================================================
// PTX helpers
// ============================================================================
__device__ __forceinline__ uint32_t smem_u32(const void* p) {
    uint32_t a;
    asm("{ .reg .u64 t; cvta.to.shared.u64 t, %1; cvt.u32.u64 %0, t; }" : "=r"(a) : "l"(p));
    return a;
}

__device__ __forceinline__ void cp16(uint32_t dst, const void* src) {
    asm volatile("cp.async.cg.shared.global [%0], [%1], 16;" :: "r"(dst), "l"(src));
}

#define CP_COMMIT()  asm volatile("cp.async.commit_group;" ::: "memory")
#define CP_WAIT(n)   asm volatile("cp.async.wait_group %0;" :: "n"(n) : "memory")

// ldmatrix x4: each 32-bit lane word = one tf32 element; tile = 8 rows x 16B
__device__ __forceinline__ void ldsm_x4(uint32_t* r, uint32_t addr) {
    asm volatile("ldmatrix.sync.aligned.m8n8.x4.shared.b16 {%0,%1,%2,%3}, [%4];"
                 : "=r"(r[0]), "=r"(r[1]), "=r"(r[2]), "=r"(r[3]) : "r"(addr));
}

__device__ __forceinline__ void mma_tf32(float* c, const uint32_t* a, const uint32_t* b) {
    asm volatile(
        "mma.sync.aligned.m16n8k8.row.col.f32.tf32.tf32.f32 "
        "{%0,%1,%2,%3}, {%4,%5,%6,%7}, {%8,%9}, {%0,%1,%2,%3};"
        : "+f"(c[0]), "+f"(c[1]), "+f"(c[2]), "+f"(c[3])
        : "r"(a[0]), "r"(a[1]), "r"(a[2]), "r"(a[3]), "r"(b[0]), "r"(b[1]));
}

// ============================================================================
// K1 (fused): blocks 0..255 -> h = x @ W + b ; blocks 256.. -> rowsum(A)
// ============================================================================
__global__ void __launch_bounds__(256) pre_kernel(const float* __restrict__ A,
                                                  const float* __restrict__ x,
                                                  const float* __restrict__ W,
                                                  const float* __restrict__ bias) {
    __shared__ float xs[32][128];
    __shared__ float red[8];
    const int tid = threadIdx.x;

    if (blockIdx.x < 256) {
        const int r0 = blockIdx.x * 32;
        const float4* xsrc = (const float4*)(x + (size_t)r0 * DD);
        float4* xdst = (float4*)&xs[0][0];
        for (int idx = tid; idx < 32 * 32; idx += 256) xdst[idx] = xsrc[idx];
        __syncthreads();

        const int n = tid & 127;
        const int rbase = (tid >> 7) * 16;
        const float b = bias[n];
        float acc[16];
#pragma unroll
        for (int r = 0; r < 16; r++) acc[r] = b;
        for (int k = 0; k < 128; k++) {
            float w = W[k * DD + n];
#pragma unroll
            for (int r = 0; r < 16; r++) acc[r] = fmaf(xs[rbase + r][k], w, acc[r]);
        }
#pragma unroll
        for (int r = 0; r < 16; r++) g_h[(size_t)(r0 + rbase + r) * DD + n] = acc[r];
    } else {
        const int i = blockIdx.x - 256;
        const float4* row = (const float4*)(A + (size_t)i * NN);
        float s = 0.f;
#pragma unroll 4
        for (int c = tid; c < NN / 4; c += 256) {
            float4 v = row[c];
            s += (v.x + v.y) + (v.z + v.w);
        }
#pragma unroll
        for (int o = 16; o; o >>= 1) s += __shfl_down_sync(0xffffffffu, s, o);
        if ((tid & 31) == 0) red[tid >> 5] = s;
        __syncthreads();
        if (tid == 0) {
            float tot = 0.f;
#pragma unroll
            for (int w = 0; w < 8; w++) tot += red[w];
            float aii = A[(size_t)i * NN + i];
            tot = tot - aii + 1.0f;
            float di = rsqrtf(tot);
            g_d[i] = di;
            g_e[i] = di * (1.0f - aii);
        }
    }
}

// ============================================================================
// K2: g = D*h (fp32) and gT = tf32_rna(g)^T  (GEMM B operand, 128 x 8192)
// ============================================================================
__global__ void __launch_bounds__(256) scale_transpose_kernel() {
    __shared__ float t[32][33];
    const int i0 = blockIdx.x * 32;
    const int n0 = blockIdx.y * 32;
    const int tx = threadIdx.x, ty = threadIdx.y;

    for (int r = ty; r < 32; r += 8) {
        int i = i0 + r;
        float v = g_h[(size_t)i * DD + n0 + tx] * g_d[i];
        g_g[(size_t)i * DD + n0 + tx] = v;
        t[r][tx] = v;
    }
    __syncthreads();
    for (int r = ty; r < 32; r += 8) {
        float v = t[tx][r];
        uint32_t tf;
        asm("cvt.rna.tf32.f32 %0, %1;" : "=r"(tf) : "f"(v));
        g_gT[(size_t)(n0 + r) * NN + i0 + tx] = __uint_as_float(tf);
    }
}

// ============================================================================
// K3: partial = A[:, split] @ g[split]  (split-K tf32 mma.sync GEMM)
//   CTA tile 256x128, 16 warps (8m x 2n), warp tile 32x64, BK=32,
//   4-stage cp.async pipeline, ldmatrix.x4 loads, 1 CTA/SM (221KB smem).
// ============================================================================
__global__ void __launch_bounds__(GTHREADS, 1) gcn_gemm(const float* __restrict__ A)
{
    extern __shared__ float smem[];
    const int tid = threadIdx.x;
    const int wid = tid >> 5;
    const int lane = tid & 31;
    const int gid = lane >> 2;
    const int tg  = lane & 3;
    const int m0 = blockIdx.x * BM;
    const int split = blockIdx.y;
    const int kbase = split * KCHUNK;
    float* __restrict__ part = g_p[split];

    const int wm = wid & 7;        // 8 warps along M
    const int wn = wid >> 3;       // 2 warps along N
    const int mwb = wm * 32;
    const int nwb = wn * 64;

    const uint32_t smem_base = smem_u32(smem);

    const int l7  = lane & 7;
    const int l8  = (lane >> 3) & 1;
    const int l16 = (lane >> 4) & 1;
    // A: two m16xk8 tiles (rows mwb..mwb+31)
    const uint32_t a_off0 = (uint32_t)(((mwb + l7 + l8 * 8) * APAD + l16 * 4) * 4);
    const uint32_t a_off1 = a_off0 + 16u * APAD * 4u;
    // B: four n16xk8 tiles (rows nwb..nwb+63)
    const uint32_t b_off0 = (uint32_t)(((nwb + l16 * 8 + l7) * APAD + l8 * 4) * 4);
    const uint32_t b_off1 = b_off0 + 16u * APAD * 4u;
    const uint32_t b_off2 = b_off0 + 32u * APAD * 4u;
    const uint32_t b_off3 = b_off0 + 48u * APAD * 4u;

    // ---------------- cp.async stage fill ----------------
    // 3072 chunks of 16B per stage: A = 2048 (256 rows x 8), B = 1024 (128 x 8)
    auto issue_stage = [&](int kt, int slot) {
        const int k0 = kbase + kt * BK;
        const uint32_t sA = smem_base + (uint32_t)(slot * STAGE_FLOATS) * 4u;
        const uint32_t sB = sA + AS_FLOATS * 4u;
#pragma unroll
        for (int j = 0; j < 6; j++) {
            int c = tid + j * GTHREADS;
            if (c < 2048) {
                int r = c >> 3, c8 = c & 7;
                cp16(sA + (uint32_t)(r * APAD + c8 * 4) * 4u,
                     A + (size_t)(m0 + r) * NN + k0 + c8 * 4);
            } else {
                int cb = c - 2048;
                int r = cb >> 3, c8 = cb & 7;
                cp16(sB + (uint32_t)(r * APAD + c8 * 4) * 4u,
                     g_gT + (size_t)r * NN + k0 + c8 * 4);
            }
        }
    };

    float c[2][8][4];              // [m16-frag][n8-frag][quad]
#pragma unroll
    for (int mf = 0; mf < 2; mf++)
#pragma unroll
        for (int nf = 0; nf < 8; nf++)
#pragma unroll
            for (int q = 0; q < 4; q++) c[mf][nf][q] = 0.f;

#pragma unroll
    for (int s = 0; s < STAGES - 1; s++) {
        issue_stage(s, s);
        CP_COMMIT();
    }

    int slot_r = 0;
    int slot_w = STAGES - 1;

    for (int kt = 0; kt < NKT; kt++) {
        CP_WAIT(STAGES - 2);
        __syncthreads();

        int nxt = kt + STAGES - 1;
        if (nxt < NKT) issue_stage(nxt, slot_w);
        CP_COMMIT();
        if (++slot_w == STAGES) slot_w = 0;

        const uint32_t aB = smem_base + (uint32_t)(slot_r * STAGE_FLOATS) * 4u;
        const uint32_t bB = aB + AS_FLOATS * 4u;
        if (++slot_r == STAGES) slot_r = 0;

#pragma unroll
        for (int kk = 0; kk < 4; kk++) {
            const uint32_t ko = (uint32_t)kk * 32u;   // 8 floats = 32 bytes
            uint32_t a0[4], a1[4], b[16];
            ldsm_x4(a0, aB + a_off0 + ko);
            ldsm_x4(a1, aB + a_off1 + ko);
            ldsm_x4(b + 0,  bB + b_off0 + ko);   // n-frags 0,1
            ldsm_x4(b + 4,  bB + b_off1 + ko);   // n-frags 2,3
            ldsm_x4(b + 8,  bB + b_off2 + ko);   // n-frags 4,5
            ldsm_x4(b + 12, bB + b_off3 + ko);   // n-frags 6,7
#pragma unroll
            for (int nf = 0; nf < 8; nf++) {
                mma_tf32(c[0][nf], a0, b + nf * 2);
                mma_tf32(c[1][nf], a1, b + nf * 2);
            }
        }
    }

    // ---------------- epilogue: raw partial store ----------------
#pragma unroll
    for (int mf = 0; mf < 2; mf++) {
        int i0r = m0 + mwb + mf * 16 + gid;
        int i1r = i0r + 8;
#pragma unroll
        for (int nf = 0; nf < 8; nf++) {
            int n = nwb + nf * 8 + tg * 2;
            *(float2*)(part + (size_t)i0r * DD + n) = make_float2(c[mf][nf][0], c[mf][nf][1]);
            *(float2*)(part + (size_t)i1r * DD + n) = make_float2(c[mf][nf][2], c[mf][nf][3]);
        }
    }
}

// ============================================================================
// K4: out = d * sum(p[0..7]) + e * g
// ============================================================================
__global__ void __launch_bounds__(256) combine_kernel(float* __restrict__ out) {
    const int idx = blockIdx.x * 256 + threadIdx.x;      // float4 index
    const int i = (idx * 4) / DD;
    const float d = g_d[i], e = g_e[i];
    float4 s = ((const float4*)g_p[0])[idx];
#pragma unroll
    for (int p = 1; p < KSPLIT; p++) {
        const float4 v = ((const float4*)g_p[p])[idx];
        s.x += v.x; s.y += v.y; s.z += v.z; s.w += v.w;
    }
    const float4 gv = ((const float4*)g_g)[idx];
    float4 o;
    o.x = d * s.x + e * gv.x;
    o.y = d * s.y + e * gv.y;
    o.z = d * s.z + e * gv.z;
    o.w = d * s.w + e * gv.w;
    ((float4*)out)[idx] = o;
}

// ============================================================================
// Host side
// ============================================================================
extern "C" void kernel_launch(void* const* d_in, const int* in_sizes, int n_in,
                              void* d_out, int out_size) {
    const float* A    = (const float*)d_in[0];
    const float* x    = (const float*)d_in[1];
    const float* W    = (const float*)d_in[2];
    const float* bias = (const float*)d_in[3];
    float* out = (float*)d_out;

    cudaFuncSetAttribute(gcn_gemm, cudaFuncAttributeMaxDynamicSharedMemorySize, SMEM_TOTAL);

    pre_kernel<<<NN + 256, 256>>>(A, x, W, bias);
    scale_transpose_kernel<<<dim3(NN / 32, DD / 32), dim3(32, 8)>>>();
    gcn_gemm<<<dim3(NN / BM, KSPLIT), GTHREADS, SMEM_TOTAL>>>(A);
    combine_kernel<<<(NN * DD / 4) / 256, 256>>>(out);
}

// round 9
// speedup vs baseline: 1.8370x; 1.2351x over previous
#include <cuda_runtime.h>
#include <cuda.h>
#include <cstdint>

// ============================================================================
// Problem constants
// ============================================================================
#define NN      8192
#define DD      128

// GEMM config: dual-plane int8 mma.sync m16n8k32
// CTA tile 128x128, 16 warps (4m x 4n), warp tile 32x32, BK=64
#define BM      128
#define BN      128
#define BK      64
#define STAGES  6
#define KSPLIT  4
#define KCHUNK  (NN / KSPLIT)          // 2048
#define NKT     (KCHUNK / BK)          // 32 K iterations per CTA
#define GTHREADS 512                   // 16 warps

// SMEM: rows of 64 data bytes + 16 pad (conflict-free ldmatrix, 16B aligned)
#define RSTRIDE 80
#define A_BYTES   (BM * RSTRIDE)               // 10240
#define BP_BYTES  (BN * RSTRIDE)               // 10240 per plane
#define BH_OFF    A_BYTES
#define BL_OFF    (A_BYTES + BP_BYTES)
#define STAGE_BYTES (A_BYTES + 2 * BP_BYTES)   // 30720
#define SMEM_TOTAL  (STAGES * STAGE_BYTES)     // 184320 (1 CTA/SM)

// ============================================================================
// Scratch (device globals; allocation-free)
// ============================================================================
__device__ __align__(1024) float  g_h[NN * DD];
__device__ __align__(1024) float  g_g[NN * DD];
__device__ __align__(1024) int8_t g_A8[(size_t)NN * NN];
__device__ __align__(1024) int8_t g_hi[(size_t)DD * NN];
__device__ __align__(1024) int8_t g_lo[(size_t)DD * NN];
__device__ __align__(1024) float  g_p[KSPLIT][NN * DD];
__device__ __align__(128)  float  g_d[NN];
__device__ __align__(128)  float  g_e[NN];
__device__ __align__(128)  unsigned int g_smax[DD];   // colmax |g| as uint bits

// ============================================================================
// PTX helpers
// ============================================================================
__device__ __forceinline__ uint32_t smem_u32(const void* p) {
    uint32_t a;
    asm("{ .reg .u64 t; cvta.to.shared.u64 t, %1; cvt.u32.u64 %0, t; }" : "=r"(a) : "l"(p));
    return a;
}

__device__ __forceinline__ void cp16(uint32_t dst, const void* src) {
    asm volatile("cp.async.cg.shared.global [%0], [%1], 16;" :: "r"(dst), "l"(src));
}

#define CP_COMMIT()  asm volatile("cp.async.commit_group;" ::: "memory")
#define CP_WAIT(n)   asm volatile("cp.async.wait_group %0;" :: "n"(n) : "memory")

// ldmatrix x4: 4 tiles of 8 rows x 16 bytes; lane l in tile t <- (row l>>2, bytes (l&3)*4)
__device__ __forceinline__ void ldsm_x4(uint32_t* r, uint32_t addr) {
    asm volatile("ldmatrix.sync.aligned.m8n8.x4.shared.b16 {%0,%1,%2,%3}, [%4];"
                 : "=r"(r[0]), "=r"(r[1]), "=r"(r[2]), "=r"(r[3]) : "r"(addr));
}

__device__ __forceinline__ void imma(int* c, const uint32_t* a, const uint32_t* b) {
    asm volatile(
        "mma.sync.aligned.m16n8k32.row.col.s32.s8.s8.s32 "
        "{%0,%1,%2,%3}, {%4,%5,%6,%7}, {%8,%9}, {%0,%1,%2,%3};"
        : "+r"(c[0]), "+r"(c[1]), "+r"(c[2]), "+r"(c[3])
        : "r"(a[0]), "r"(a[1]), "r"(a[2]), "r"(a[3]), "r"(b[0]), "r"(b[1]));
}

// ============================================================================
// K1 (fused): blocks 0..255 -> h = x @ W + b ; blocks 256.. -> rowsum(A) + A8
// ============================================================================
__global__ void __launch_bounds__(256) pre_kernel(const float* __restrict__ A,
                                                  const float* __restrict__ x,
                                                  const float* __restrict__ W,
                                                  const float* __restrict__ bias) {
    __shared__ float xs[32][128];
    __shared__ float red[8];
    const int tid = threadIdx.x;

    if (blockIdx.x < 256) {
        const int r0 = blockIdx.x * 32;
        const float4* xsrc = (const float4*)(x + (size_t)r0 * DD);
        float4* xdst = (float4*)&xs[0][0];
        for (int idx = tid; idx < 32 * 32; idx += 256) xdst[idx] = xsrc[idx];
        __syncthreads();

        const int n = tid & 127;
        const int rbase = (tid >> 7) * 16;
        const float b = bias[n];
        float acc[16];
#pragma unroll
        for (int r = 0; r < 16; r++) acc[r] = b;
        for (int k = 0; k < 128; k++) {
            float w = W[k * DD + n];
#pragma unroll
            for (int r = 0; r < 16; r++) acc[r] = fmaf(xs[rbase + r][k], w, acc[r]);
        }
#pragma unroll
        for (int r = 0; r < 16; r++) g_h[(size_t)(r0 + rbase + r) * DD + n] = acc[r];
    } else {
        const int i = blockIdx.x - 256;
        const float4* row = (const float4*)(A + (size_t)i * NN);
        char4* a8row = (char4*)(g_A8 + (size_t)i * NN);
        float s = 0.f;
#pragma unroll 4
        for (int c = tid; c < NN / 4; c += 256) {
            float4 v = row[c];
            s += (v.x + v.y) + (v.z + v.w);
            char4 q;
            q.x = (char)v.x; q.y = (char)v.y; q.z = (char)v.z; q.w = (char)v.w;
            a8row[c] = q;
        }
#pragma unroll
        for (int o = 16; o; o >>= 1) s += __shfl_down_sync(0xffffffffu, s, o);
        if ((tid & 31) == 0) red[tid >> 5] = s;
        __syncthreads();
        if (tid == 0) {
            float tot = 0.f;
#pragma unroll
            for (int w = 0; w < 8; w++) tot += red[w];
            float aii = A[(size_t)i * NN + i];
            tot = tot - aii + 1.0f;
            float di = rsqrtf(tot);
            g_d[i] = di;
            g_e[i] = di * (1.0f - aii);
        }
    }
}

// ============================================================================
// K2: g = d*h ; column max |g| -> g_smax (atomicMax on float bits, values >= 0)
// ============================================================================
__global__ void __launch_bounds__(256) scale_colmax_kernel() {
    __shared__ float sm[256];
    const int tid = threadIdx.x;
    const int col = tid & 127;
    const int half = tid >> 7;
    const int ibase = blockIdx.x * 64 + half * 32;
    float m = 0.f;
#pragma unroll 4
    for (int r = 0; r < 32; r++) {
        int i = ibase + r;
        float v = g_h[(size_t)i * DD + col] * g_d[i];
        g_g[(size_t)i * DD + col] = v;
        m = fmaxf(m, fabsf(v));
    }
    sm[tid] = m;
    __syncthreads();
    if (tid < 128)
        atomicMax(&g_smax[col], __float_as_uint(fmaxf(sm[tid], sm[tid + 128])));
}

// ============================================================================
// K3: quantize + transpose: g -> hi/lo planes [n][i] int8
//   q = g/fs (fs = smax/127), hi = rint(q), lo = rint((q-hi)*254)
// ============================================================================
__global__ void __launch_bounds__(256) quant_transpose_kernel() {
    __shared__ float t[32][33];
    const int i0 = blockIdx.x * 32;
    const int n0 = blockIdx.y * 32;
    const int tx = threadIdx.x, ty = threadIdx.y;

    for (int r = ty; r < 32; r += 8)
        t[r][tx] = g_g[(size_t)(i0 + r) * DD + n0 + tx];
    __syncthreads();
    for (int r = ty; r < 32; r += 8) {
        int n = n0 + r;
        float inv = 127.f / __uint_as_float(g_smax[n]);
        float q = t[tx][r] * inv;                     // g[i0+tx][n]
        float hi = rintf(q);
        hi = fminf(fmaxf(hi, -127.f), 127.f);
        float lo = rintf((q - hi) * 254.f);
        lo = fminf(fmaxf(lo, -127.f), 127.f);
        g_hi[(size_t)n * NN + i0 + tx] = (int8_t)hi;
        g_lo[(size_t)n * NN + i0 + tx] = (int8_t)lo;
    }
}

// ============================================================================
// K4: partial = fs_n * (A8 @ hi + (A8 @ lo)/254)  per K-split (s32 exact MMA)
//   CTA 128x128, 16 warps (4m x 4n), warp tile 32x32, BK=64, 6-stage cp.async.
// ============================================================================
__global__ void __launch_bounds__(GTHREADS, 1) gcn_gemm()
{
    extern __shared__ char smem[];
    const int tid = threadIdx.x;
    const int wid = tid >> 5;
    const int lane = tid & 31;
    const int gid = lane >> 2;
    const int tg  = lane & 3;
    const int m0 = blockIdx.x * BM;
    const int split = blockIdx.y;
    const int kbase = split * KCHUNK;
    float* __restrict__ part = g_p[split];

    const int mwb = (wid & 3) * 32;     // 4 warps along M
    const int nwb = (wid >> 2) * 32;    // 4 warps along N

    const uint32_t smem_base = smem_u32(smem);

    const int l7  = lane & 7;
    const int l8  = (lane >> 3) & 1;
    const int l16 = (lane >> 4) & 1;
    // A fragment tiles: lanes0-7 rows+0 b0, 8-15 rows+8 b0, 16-23 rows+0 b16, 24-31 rows+8 b16
    const uint32_t a_off0 = (uint32_t)((mwb + l7 + l8 * 8) * RSTRIDE + l16 * 16);
    const uint32_t a_off1 = a_off0 + 16u * RSTRIDE;
    // B tiles: lanes0-7 n+0 b0, 8-15 n+0 b16, 16-23 n+8 b0, 24-31 n+8 b16
    const uint32_t b_off0 = (uint32_t)((nwb + l7 + l16 * 8) * RSTRIDE + l8 * 16);
    const uint32_t b_off1 = b_off0 + 16u * RSTRIDE;

    // -------- cp.async stage fill: 1536 x 16B (A 512, Bhi 512, Blo 512) --------
    auto issue_stage = [&](int kt, int slot) {
        const int k0 = kbase + kt * BK;
        const uint32_t st = smem_base + (uint32_t)slot * STAGE_BYTES;
#pragma unroll
        for (int j = 0; j < 3; j++) {
            int c = tid + j * GTHREADS;
            int r = (c >> 2) & 127, c4 = c & 3;
            if (c < 512) {
                cp16(st + (uint32_t)(r * RSTRIDE + c4 * 16),
                     g_A8 + (size_t)(m0 + r) * NN + k0 + c4 * 16);
            } else if (c < 1024) {
                cp16(st + BH_OFF + (uint32_t)(r * RSTRIDE + c4 * 16),
                     g_hi + (size_t)r * NN + k0 + c4 * 16);
            } else {
                cp16(st + BL_OFF + (uint32_t)(r * RSTRIDE + c4 * 16),
                     g_lo + (size_t)r * NN + k0 + c4 * 16);
            }
        }
    };

    int ch[2][4][4], cl[2][4][4];
#pragma unroll
    for (int mf = 0; mf < 2; mf++)
#pragma unroll
        for (int nf = 0; nf < 4; nf++)
#pragma unroll
            for (int q = 0; q < 4; q++) { ch[mf][nf][q] = 0; cl[mf][nf][q] = 0; }

#pragma unroll
    for (int s = 0; s < STAGES - 1; s++) {
        issue_stage(s, s);
        CP_COMMIT();
    }

    int slot_r = 0;
    int slot_w = STAGES - 1;

    for (int kt = 0; kt < NKT; kt++) {
        CP_WAIT(STAGES - 2);
        __syncthreads();

        int nxt = kt + STAGES - 1;
        if (nxt < NKT) issue_stage(nxt, slot_w);
        CP_COMMIT();
        if (++slot_w == STAGES) slot_w = 0;

        const uint32_t stg = smem_base + (uint32_t)slot_r * STAGE_BYTES;
        if (++slot_r == STAGES) slot_r = 0;

#pragma unroll
        for (int ks = 0; ks < 2; ks++) {
            const uint32_t ko = (uint32_t)ks * 32u;    // k32 step = 32 bytes
            uint32_t a0[4], a1[4], bh[8], bl[8];
            ldsm_x4(a0, stg + a_off0 + ko);
            ldsm_x4(a1, stg + a_off1 + ko);
            ldsm_x4(bh,     stg + BH_OFF + b_off0 + ko);   // nf0, nf1
            ldsm_x4(bh + 4, stg + BH_OFF + b_off1 + ko);   // nf2, nf3
            ldsm_x4(bl,     stg + BL_OFF + b_off0 + ko);
            ldsm_x4(bl + 4, stg + BL_OFF + b_off1 + ko);
#pragma unroll
            for (int nf = 0; nf < 4; nf++) {
                imma(ch[0][nf], a0, bh + nf * 2);
                imma(ch[1][nf], a1, bh + nf * 2);
                imma(cl[0][nf], a0, bl + nf * 2);
                imma(cl[1][nf], a1, bl + nf * 2);
            }
        }
    }

    // -------- epilogue: p = fs_n * (S_hi + S_lo/254), store f32 partial --------
    const float inv254 = 1.f / 254.f;
#pragma unroll
    for (int mf = 0; mf < 2; mf++) {
        int i0r = m0 + mwb + mf * 16 + gid;
        int i1r = i0r + 8;
#pragma unroll
        for (int nf = 0; nf < 4; nf++) {
            int n = nwb + nf * 8 + tg * 2;
            float fs0 = __uint_as_float(g_smax[n])     * (1.f / 127.f);
            float fs1 = __uint_as_float(g_smax[n + 1]) * (1.f / 127.f);
            float2 p0, p1;
            p0.x = fs0 * ((float)ch[mf][nf][0] + (float)cl[mf][nf][0] * inv254);
            p0.y = fs1 * ((float)ch[mf][nf][1] + (float)cl[mf][nf][1] * inv254);
            p1.x = fs0 * ((float)ch[mf][nf][2] + (float)cl[mf][nf][2] * inv254);
            p1.y = fs1 * ((float)ch[mf][nf][3] + (float)cl[mf][nf][3] * inv254);
            *(float2*)(part + (size_t)i0r * DD + n) = p0;
            *(float2*)(part + (size_t)i1r * DD + n) = p1;
        }
    }
}

// ============================================================================
// K5: out = d * sum(p[0..KSPLIT-1]) + e * g
// ============================================================================
__global__ void __launch_bounds__(256) combine_kernel(float* __restrict__ out) {
    const int idx = blockIdx.x * 256 + threadIdx.x;      // float4 index
    const int i = (idx * 4) / DD;
    const float d = g_d[i], e = g_e[i];
    float4 s = ((const float4*)g_p[0])[idx];
#pragma unroll
    for (int p = 1; p < KSPLIT; p++) {
        const float4 v = ((const float4*)g_p[p])[idx];
        s.x += v.x; s.y += v.y; s.z += v.z; s.w += v.w;
    }
    const float4 gv = ((const float4*)g_g)[idx];
    float4 o;
    o.x = d * s.x + e * gv.x;
    o.y = d * s.y + e * gv.y;
    o.z = d * s.z + e * gv.z;
    o.w = d * s.w + e * gv.w;
    ((float4*)out)[idx] = o;
}

// ============================================================================
// Host side
// ============================================================================
extern "C" void kernel_launch(void* const* d_in, const int* in_sizes, int n_in,
                              void* d_out, int out_size) {
    const float* A    = (const float*)d_in[0];
    const float* x    = (const float*)d_in[1];
    const float* W    = (const float*)d_in[2];
    const float* bias = (const float*)d_in[3];
    float* out = (float*)d_out;

    cudaFuncSetAttribute(gcn_gemm, cudaFuncAttributeMaxDynamicSharedMemorySize, SMEM_TOTAL);

    pre_kernel<<<NN + 256, 256>>>(A, x, W, bias);
    scale_colmax_kernel<<<NN / 64, 256>>>();
    quant_transpose_kernel<<<dim3(NN / 32, DD / 32), dim3(32, 8)>>>();
    gcn_gemm<<<dim3(NN / BM, KSPLIT), GTHREADS, SMEM_TOTAL>>>();
    combine_kernel<<<(NN * DD / 4) / 256, 256>>>(out);
}